// round 1
// baseline (speedup 1.0000x reference)
#include <cuda_runtime.h>

// AssociatorLoss: B=32, N=32
//   one[b,i,j,k,l] = sum_m a[b,i,m,l] * a[b,j,k,m]
//   two[b,i,j,k,l] = sum_m a[b,m,k,l] * a[b,i,j,m]
//   KL = sum two * (log(two) - log(one)) / B  =  sum two * log(two/one) / B
//
// CTA = (b,i). Stage the full a[b] cube (128 KB) into SMEM with an XOR
// swizzle on float4 chunks within each 32-float row, so both row-major and
// "transposed" (a[b,m,k,:] across lanes k) reads are conflict-free.
// Thread tile: 4 j-values x 8 l-values; both dot products accumulated in
// registers in one merged m-loop; KL reduced with an accurate (~1e-7 abs)
// range-reduced log so the 33M-term sum stays well inside rel_err 1e-3.

__device__ float g_partial[1024];

// Accurate natural log: reduce to z in [sqrt(2)/2, sqrt(2)), atanh series.
// |abs error| ~ 1e-7 over the full float range we see here.
__device__ __forceinline__ float acc_logf(float x) {
    int ix = __float_as_int(x);
    int t  = ix - 0x3f3504f3;             // boundary at sqrt(2)/2
    int e  = t >> 23;                     // arithmetic shift: exponent
    float z = __int_as_float(ix - (t & 0xff800000));  // z in [0.7071, 1.4142)
    float f = z - 1.0f;                   // f in [-0.2929, 0.4142]
    float s = __fdividef(f, 2.0f + f);    // |s| <= 0.1716
    float s2 = s * s;
    // log(z) = 2s + (2/3)s^3 + (2/5)s^5 + (2/7)s^7  (remainder ~3e-8)
    float p = fmaf(s2, fmaf(s2, fmaf(s2, 0.28571429f, 0.4f), 0.66666667f), 2.0f);
    return fmaf((float)e, 0.69314718f, s * p);
}

__global__ __launch_bounds__(512, 1)
void assoc_kernel(const float* __restrict__ A) {
    extern __shared__ float4 sc[];        // 8192 float4 = 128 KB, swizzled cube

    const int i = blockIdx.x;             // 0..31
    const int b = blockIdx.y;             // 0..31
    const float4* ab4 = reinterpret_cast<const float4*>(A + b * 32768);
    const int tid = threadIdx.x;

    // ---- stage a[b] into SMEM, swizzled: chunk c of row r -> c ^ (r & 7) ----
    #pragma unroll
    for (int it = 0; it < 16; ++it) {
        int g = it * 512 + tid;                       // coalesced float4 index
        float4 v = ab4[g];
        int pos = (g & ~7) | ((g ^ (g >> 3)) & 7);    // row*8 + (c ^ (row&7))
        sc[pos] = v;
    }
    __syncthreads();

    const int k   = tid & 31;        // lane = k
    const int jg  = (tid >> 5) & 7;  // 8 j-groups of 4
    const int lh  = tid >> 8;        // l-half (0/1), each covers 2 l-chunks
    const int jb  = jg * 4;
    const int ks  = k & 7;

    float kl = 0.0f;

    #pragma unroll
    for (int lgi = 0; lgi < 2; ++lgi) {
        const int lg = lh * 2 + lgi;          // l-chunk of 8: l = lg*8 + lw
        const int c0 = lg * 2, c1 = lg * 2 + 1;

        float acc1[4][8], acc2[4][8];
        #pragma unroll
        for (int jj = 0; jj < 4; ++jj)
            #pragma unroll
            for (int lw = 0; lw < 8; ++lw) { acc1[jj][lw] = 0.0f; acc2[jj][lw] = 0.0f; }

        #pragma unroll
        for (int mc = 0; mc < 8; ++mc) {      // m = mc*4 + mm
            float4 rm4[4], aj4[4];
            #pragma unroll
            for (int jj = 0; jj < 4; ++jj) {
                int j = jb + jj;
                // rm4[jj] = a[b, j, k, mc*4 .. mc*4+3]   (row j*32+k)
                rm4[jj] = sc[(j * 32 + k) * 8 + (mc ^ ks)];
                // aj4[jj] = a[b, i, j, mc*4 .. mc*4+3]   (row i*32+j, broadcast)
                aj4[jj] = sc[(i * 32 + j) * 8 + (mc ^ (j & 7))];
            }

            #define MM_STEP(MM)                                                     \
            {                                                                        \
                const int m = mc * 4 + (MM);                                         \
                const int ms = m & 7;                                                \
                float4 s0 = sc[(i * 32 + m) * 8 + (c0 ^ ms)];  /* a[b,i,m,l] bc */   \
                float4 s1 = sc[(i * 32 + m) * 8 + (c1 ^ ms)];                        \
                float4 v0 = sc[(m * 32 + k) * 8 + (c0 ^ ks)];  /* a[b,m,k,l]   */    \
                float4 v1 = sc[(m * 32 + k) * 8 + (c1 ^ ks)];                        \
                _Pragma("unroll")                                                    \
                for (int jj = 0; jj < 4; ++jj) {                                     \
                    float aj = ((const float*)&aj4[jj])[(MM)];                       \
                    float rv = ((const float*)&rm4[jj])[(MM)];                       \
                    acc2[jj][0] = fmaf(aj, v0.x, acc2[jj][0]);                       \
                    acc2[jj][1] = fmaf(aj, v0.y, acc2[jj][1]);                       \
                    acc2[jj][2] = fmaf(aj, v0.z, acc2[jj][2]);                       \
                    acc2[jj][3] = fmaf(aj, v0.w, acc2[jj][3]);                       \
                    acc2[jj][4] = fmaf(aj, v1.x, acc2[jj][4]);                       \
                    acc2[jj][5] = fmaf(aj, v1.y, acc2[jj][5]);                       \
                    acc2[jj][6] = fmaf(aj, v1.z, acc2[jj][6]);                       \
                    acc2[jj][7] = fmaf(aj, v1.w, acc2[jj][7]);                       \
                    acc1[jj][0] = fmaf(rv, s0.x, acc1[jj][0]);                       \
                    acc1[jj][1] = fmaf(rv, s0.y, acc1[jj][1]);                       \
                    acc1[jj][2] = fmaf(rv, s0.z, acc1[jj][2]);                       \
                    acc1[jj][3] = fmaf(rv, s0.w, acc1[jj][3]);                       \
                    acc1[jj][4] = fmaf(rv, s1.x, acc1[jj][4]);                       \
                    acc1[jj][5] = fmaf(rv, s1.y, acc1[jj][5]);                       \
                    acc1[jj][6] = fmaf(rv, s1.z, acc1[jj][6]);                       \
                    acc1[jj][7] = fmaf(rv, s1.w, acc1[jj][7]);                       \
                }                                                                    \
            }
            MM_STEP(0) MM_STEP(1) MM_STEP(2) MM_STEP(3)
            #undef MM_STEP
        }

        // ---- KL for this 4x8 tile: two * log(two/one) ----
        #pragma unroll
        for (int jj = 0; jj < 4; ++jj)
            #pragma unroll
            for (int lw = 0; lw < 8; ++lw) {
                float two = acc2[jj][lw];
                float one = acc1[jj][lw];
                float q = __fdividef(two, one);
                kl = fmaf(two, acc_logf(q), kl);
            }
    }

    // ---- deterministic block reduction ----
    #pragma unroll
    for (int o = 16; o > 0; o >>= 1)
        kl += __shfl_xor_sync(0xffffffffu, kl, o);

    __syncthreads();                       // smem reuse safe after all reads done
    float* sred = reinterpret_cast<float*>(sc);
    if ((tid & 31) == 0) sred[tid >> 5] = kl;
    __syncthreads();
    if (tid < 16) {
        float v = sred[tid];
        #pragma unroll
        for (int o = 8; o > 0; o >>= 1)
            v += __shfl_xor_sync(0xffffu, v, o);
        if (tid == 0) g_partial[b * 32 + i] = v;
    }
}

__global__ void reduce_kernel(float* __restrict__ out) {
    __shared__ double sd[256];
    int tid = threadIdx.x;
    double s = 0.0;
    #pragma unroll
    for (int it = 0; it < 4; ++it)
        s += (double)g_partial[it * 256 + tid];
    sd[tid] = s;
    __syncthreads();
    #pragma unroll
    for (int o = 128; o > 0; o >>= 1) {
        if (tid < o) sd[tid] += sd[tid + o];
        __syncthreads();
    }
    if (tid == 0) out[0] = (float)(sd[0] * (1.0 / 32.0));   // / B
}

extern "C" void kernel_launch(void* const* d_in, const int* in_sizes, int n_in,
                              void* d_out, int out_size) {
    const float* A = (const float*)d_in[0];
    float* out = (float*)d_out;

    cudaFuncSetAttribute(assoc_kernel,
                         cudaFuncAttributeMaxDynamicSharedMemorySize, 131072);

    dim3 grid(32, 32);   // (i, b)
    assoc_kernel<<<grid, 512, 131072>>>(A);
    reduce_kernel<<<1, 256>>>(out);
}